// round 4
// baseline (speedup 1.0000x reference)
#include <cuda_runtime.h>
#include <cuda_bf16.h>

// LIF scan, T=4, V_RESET=0, TAU=2, forward spike = heaviside(v_charged - 1).
// R4: persistent grid-stride kernel (grid = SMs * 8 CTAs, ~16 iters/thread).
// Removes ~15 wave transitions and keeps the DRAM pipe continuously fed:
// next iteration's independent loads overlap previous iteration's stores.
// Memory-bound: ~620 MB total traffic; target = LTS streaming ceiling.

#define T_STEPS 4

__device__ __forceinline__ void lif_step(float& v, float x, float& s) {
    // Match reference arithmetic exactly: v_charged = v + (x - v)/2
    float vc = fmaf(x - v, 0.5f, v);
    bool sp = (vc >= 1.0f);           // v_charged - V_THRESHOLD >= 0
    s = sp ? 1.0f : 0.0f;
    v = sp ? 0.0f : vc;               // hard reset to V_RESET=0
}

__global__ void __launch_bounds__(256)
lif_kernel(const float4* __restrict__ x, float4* __restrict__ out, int n4) {
    int stride = gridDim.x * blockDim.x;

    for (int i = blockIdx.x * blockDim.x + threadIdx.x; i < n4; i += stride) {
        // Front-batched loads: independent of the v-chain (MLP=4 per iter,
        // and overlapped with the previous iteration's stores).
        float4 x0 = __ldcs(x + i);
        float4 x1 = __ldcs(x + i + (size_t)n4);
        float4 x2 = __ldcs(x + i + (size_t)2 * n4);
        float4 x3 = __ldcs(x + i + (size_t)3 * n4);

        float4 s0, s1, s2, s3;

        {
            float v = 0.0f;
            lif_step(v, x0.x, s0.x); lif_step(v, x1.x, s1.x);
            lif_step(v, x2.x, s2.x); lif_step(v, x3.x, s3.x);
        }
        {
            float v = 0.0f;
            lif_step(v, x0.y, s0.y); lif_step(v, x1.y, s1.y);
            lif_step(v, x2.y, s2.y); lif_step(v, x3.y, s3.y);
        }
        {
            float v = 0.0f;
            lif_step(v, x0.z, s0.z); lif_step(v, x1.z, s1.z);
            lif_step(v, x2.z, s2.z); lif_step(v, x3.z, s3.z);
        }
        {
            float v = 0.0f;
            lif_step(v, x0.w, s0.w); lif_step(v, x1.w, s1.w);
            lif_step(v, x2.w, s2.w); lif_step(v, x3.w, s3.w);
        }

        __stcs(out + i,                  s0);
        __stcs(out + i + (size_t)n4,     s1);
        __stcs(out + i + (size_t)2 * n4, s2);
        __stcs(out + i + (size_t)3 * n4, s3);
    }
}

extern "C" void kernel_launch(void* const* d_in, const int* in_sizes, int n_in,
                              void* d_out, int out_size) {
    const float* x = (const float*)d_in[0];
    float* out = (float*)d_out;

    int total = in_sizes[0];             // T * N = 77,463,552
    int n = total / T_STEPS;             // 19,365,888 elements per timestep
    int n4 = n / 4;                      // 4,841,472 float4 lanes

    // Persistent grid: 152 SMs on GB300, 8 CTAs/SM at 256 thr / ~30 regs.
    int threads = 256;
    int blocks = 152 * 8;                // 1216 CTAs, ~16 grid-stride iters
    lif_kernel<<<blocks, threads>>>((const float4*)x, (float4*)out, n4);
}

// round 5
// speedup vs baseline: 1.1130x; 1.1130x over previous
#include <cuda_runtime.h>
#include <cuda_bf16.h>

// LIF scan, T=4, V_RESET=0, TAU=2, forward spike = heaviside(v_charged - 1).
// R5: R1/R3 structure (1 float4/thread, 4 front-batched LDG.128, .cs hints)
// with block=128 (vs 256): halves per-CTA L1tex load burst, finer CTA
// interleave / tail balance. Memory-bound: ~620 MB total traffic.

#define T_STEPS 4

__device__ __forceinline__ void lif_step(float& v, float x, float& s) {
    // Match reference arithmetic exactly: v_charged = v + (x - v)/2
    float vc = fmaf(x - v, 0.5f, v);
    bool sp = (vc >= 1.0f);           // v_charged - V_THRESHOLD >= 0
    s = sp ? 1.0f : 0.0f;
    v = sp ? 0.0f : vc;               // hard reset to V_RESET=0
}

__global__ void __launch_bounds__(128)
lif_kernel(const float4* __restrict__ x, float4* __restrict__ out, int n4) {
    int i = blockIdx.x * blockDim.x + threadIdx.x;
    if (i >= n4) return;

    // Front-batched streaming loads: independent of the v-chain (MLP=4).
    float4 x0 = __ldcs(x + i);
    float4 x1 = __ldcs(x + i + (size_t)n4);
    float4 x2 = __ldcs(x + i + (size_t)2 * n4);
    float4 x3 = __ldcs(x + i + (size_t)3 * n4);

    float4 s0, s1, s2, s3;

    // 4 independent lanes, each a 4-step sequential scan.
    {
        float v = 0.0f;
        lif_step(v, x0.x, s0.x); lif_step(v, x1.x, s1.x);
        lif_step(v, x2.x, s2.x); lif_step(v, x3.x, s3.x);
    }
    {
        float v = 0.0f;
        lif_step(v, x0.y, s0.y); lif_step(v, x1.y, s1.y);
        lif_step(v, x2.y, s2.y); lif_step(v, x3.y, s3.y);
    }
    {
        float v = 0.0f;
        lif_step(v, x0.z, s0.z); lif_step(v, x1.z, s1.z);
        lif_step(v, x2.z, s2.z); lif_step(v, x3.z, s3.z);
    }
    {
        float v = 0.0f;
        lif_step(v, x0.w, s0.w); lif_step(v, x1.w, s1.w);
        lif_step(v, x2.w, s2.w); lif_step(v, x3.w, s3.w);
    }

    __stcs(out + i,                  s0);
    __stcs(out + i + (size_t)n4,     s1);
    __stcs(out + i + (size_t)2 * n4, s2);
    __stcs(out + i + (size_t)3 * n4, s3);
}

extern "C" void kernel_launch(void* const* d_in, const int* in_sizes, int n_in,
                              void* d_out, int out_size) {
    const float* x = (const float*)d_in[0];
    float* out = (float*)d_out;

    int total = in_sizes[0];             // T * N = 77,463,552
    int n = total / T_STEPS;             // 19,365,888 elements per timestep
    int n4 = n / 4;                      // 4,841,472 float4 lanes (768 % 4 == 0)

    int threads = 128;
    int blocks = (n4 + threads - 1) / threads;   // 37,824 CTAs
    lif_kernel<<<blocks, threads>>>((const float4*)x, (float4*)out, n4);
}

// round 6
// speedup vs baseline: 1.1253x; 1.0110x over previous
#include <cuda_runtime.h>
#include <cuda_bf16.h>

// LIF scan, T=4, V_RESET=0, TAU=2, forward spike = heaviside(v_charged - 1).
// R6: R1/R3 structure (1 float4/thread, 4 front-batched LDG.128, .cs hints)
// with block=512: fewest CTAs (9456), amortizes per-CTA preamble; warp
// residency per SM unchanged (64 warps). Memory-bound: ~620 MB traffic.
// Measured knob slope: block 128 -> 87.58us, 256 -> 86.66us; probing 512.

#define T_STEPS 4

__device__ __forceinline__ void lif_step(float& v, float x, float& s) {
    // Match reference arithmetic exactly: v_charged = v + (x - v)/2
    float vc = fmaf(x - v, 0.5f, v);
    bool sp = (vc >= 1.0f);           // v_charged - V_THRESHOLD >= 0
    s = sp ? 1.0f : 0.0f;
    v = sp ? 0.0f : vc;               // hard reset to V_RESET=0
}

__global__ void __launch_bounds__(512)
lif_kernel(const float4* __restrict__ x, float4* __restrict__ out, int n4) {
    int i = blockIdx.x * blockDim.x + threadIdx.x;
    if (i >= n4) return;

    // Front-batched streaming loads: independent of the v-chain (MLP=4).
    float4 x0 = __ldcs(x + i);
    float4 x1 = __ldcs(x + i + (size_t)n4);
    float4 x2 = __ldcs(x + i + (size_t)2 * n4);
    float4 x3 = __ldcs(x + i + (size_t)3 * n4);

    float4 s0, s1, s2, s3;

    // 4 independent lanes, each a 4-step sequential scan.
    {
        float v = 0.0f;
        lif_step(v, x0.x, s0.x); lif_step(v, x1.x, s1.x);
        lif_step(v, x2.x, s2.x); lif_step(v, x3.x, s3.x);
    }
    {
        float v = 0.0f;
        lif_step(v, x0.y, s0.y); lif_step(v, x1.y, s1.y);
        lif_step(v, x2.y, s2.y); lif_step(v, x3.y, s3.y);
    }
    {
        float v = 0.0f;
        lif_step(v, x0.z, s0.z); lif_step(v, x1.z, s1.z);
        lif_step(v, x2.z, s2.z); lif_step(v, x3.z, s3.z);
    }
    {
        float v = 0.0f;
        lif_step(v, x0.w, s0.w); lif_step(v, x1.w, s1.w);
        lif_step(v, x2.w, s2.w); lif_step(v, x3.w, s3.w);
    }

    __stcs(out + i,                  s0);
    __stcs(out + i + (size_t)n4,     s1);
    __stcs(out + i + (size_t)2 * n4, s2);
    __stcs(out + i + (size_t)3 * n4, s3);
}

extern "C" void kernel_launch(void* const* d_in, const int* in_sizes, int n_in,
                              void* d_out, int out_size) {
    const float* x = (const float*)d_in[0];
    float* out = (float*)d_out;

    int total = in_sizes[0];             // T * N = 77,463,552
    int n = total / T_STEPS;             // 19,365,888 elements per timestep
    int n4 = n / 4;                      // 4,841,472 float4 lanes (768 % 4 == 0)

    int threads = 512;
    int blocks = (n4 + threads - 1) / threads;   // 9,456 CTAs
    lif_kernel<<<blocks, threads>>>((const float4*)x, (float4*)out, n4);
}